// round 12
// baseline (speedup 1.0000x reference)
#include <cuda_runtime.h>
#include <cuda_bf16.h>
#include <math.h>
#include <stdint.h>

// Problem constants
#define PB   8
#define PF   16
#define PNS  196
#define PJ   24
#define PH   8
#define PDH  64
#define PDIM 512
#define PROT 32
#define PN   (PJ + PF * PNS)   // 3160
#define PBH  (PB * PH)         // 64
#define PM1  (PB * PN)         // 25280
#define NKEY (PJ + PNS)        // 220
#define NQKV (3 * PDIM)        // 1536

// -------------------- scratch (device globals) ------------------------------
__device__ __align__(16) float g_q[(size_t)PBH * PN * PDH];
__device__ __align__(16) float g_k[(size_t)PBH * PN * PDH];
__device__ __align__(16) float g_v[(size_t)PBH * PN * PDH];
__device__ __align__(16) float g_o[(size_t)PB * PN * (PH * PDH)];

__device__ __align__(16) __nv_bfloat16 g_xhi[(size_t)(PM1 + 128) * PDIM];
__device__ __align__(16) __nv_bfloat16 g_xlo[(size_t)(PM1 + 128) * PDIM];
__device__ __align__(16) __nv_bfloat16 g_ohi[(size_t)(PM1 + 128) * PDIM];
__device__ __align__(16) __nv_bfloat16 g_olo[(size_t)(PM1 + 128) * PDIM];
__device__ __align__(16) __nv_bfloat16 g_wqkvT_hi[(size_t)NQKV * PDIM];  // [N][K]
__device__ __align__(16) __nv_bfloat16 g_wqkvT_lo[(size_t)NQKV * PDIM];
__device__ __align__(16) __nv_bfloat16 g_woutT_hi[(size_t)PDIM * PDIM];  // [N][K]
__device__ __align__(16) __nv_bfloat16 g_woutT_lo[(size_t)PDIM * PDIM];

// joints attention scratch
__device__ __align__(16) float g_jp[(size_t)PBH * PJ * PN];
__device__ __align__(16) float g_jout[4 * PBH * PJ * PDH];
__device__ __align__(16) float g_jpsum[4 * PBH * PJ];

#define JCHUNK 792

// -------------------- asm helpers -------------------------------------------
__device__ __forceinline__ uint32_t smem_to_u32(const void* p) {
    uint32_t a;
    asm("{ .reg .u64 t; cvta.to.shared.u64 t, %1; cvt.u32.u64 %0, t; }" : "=r"(a) : "l"(p));
    return a;
}
__device__ __forceinline__ void ldsm4(uint32_t* r, uint32_t addr) {
    asm volatile("ldmatrix.sync.aligned.m8n8.x4.shared.b16 {%0,%1,%2,%3}, [%4];"
        : "=r"(r[0]), "=r"(r[1]), "=r"(r[2]), "=r"(r[3]) : "r"(addr));
}
__device__ __forceinline__ void mma16816(float* c, const uint32_t* a, const uint32_t* b) {
    asm volatile("mma.sync.aligned.m16n8k16.row.col.f32.bf16.bf16.f32 "
        "{%0,%1,%2,%3}, {%4,%5,%6,%7}, {%8,%9}, {%0,%1,%2,%3};"
        : "+f"(c[0]), "+f"(c[1]), "+f"(c[2]), "+f"(c[3])
        : "r"(a[0]), "r"(a[1]), "r"(a[2]), "r"(a[3]), "r"(b[0]), "r"(b[1]));
}
__device__ __forceinline__ void cp_async16(uint32_t saddr, const void* gptr) {
    asm volatile("cp.async.cg.shared.global [%0], [%1], 16;"
        :: "r"(saddr), "l"(gptr) : "memory");
}
#define CP_COMMIT() asm volatile("cp.async.commit_group;" ::: "memory")
#define CP_WAIT(N)  asm volatile("cp.async.wait_group %0;" :: "n"(N) : "memory")

// -------------------- conversion kernels ------------------------------------
__global__ void convert_split_kernel(const float* __restrict__ src,
                                     __nv_bfloat16* __restrict__ hi,
                                     __nv_bfloat16* __restrict__ lo, int n4) {
    int i = blockIdx.x * blockDim.x + threadIdx.x;
    if (i >= n4) return;
    float4 v = ((const float4*)src)[i];
    __nv_bfloat16 h0 = __float2bfloat16(v.x), h1 = __float2bfloat16(v.y);
    __nv_bfloat16 h2 = __float2bfloat16(v.z), h3 = __float2bfloat16(v.w);
    hi[4 * i + 0] = h0; hi[4 * i + 1] = h1; hi[4 * i + 2] = h2; hi[4 * i + 3] = h3;
    lo[4 * i + 0] = __float2bfloat16(v.x - __bfloat162float(h0));
    lo[4 * i + 1] = __float2bfloat16(v.y - __bfloat162float(h1));
    lo[4 * i + 2] = __float2bfloat16(v.z - __bfloat162float(h2));
    lo[4 * i + 3] = __float2bfloat16(v.w - __bfloat162float(h3));
}

__global__ void convert_wT_kernel(const float* __restrict__ w,
                                  __nv_bfloat16* __restrict__ hi,
                                  __nv_bfloat16* __restrict__ lo, int K, int Nn) {
    int i = blockIdx.x * blockDim.x + threadIdx.x;
    if (i >= K * Nn) return;
    int n = i / K, k = i - n * K;
    float v = w[(size_t)k * Nn + n];
    __nv_bfloat16 h = __float2bfloat16(v);
    hi[i] = h;
    lo[i] = __float2bfloat16(v - __bfloat162float(h));
}

// -------------------- mma.sync split-bf16 GEMM (double-buffered) -------------
#define TILE_B   (128 * 144)        // 18432 bytes per operand tile
#define BUF_B    (4 * TILE_B)       // 73728 per stage
#define GEMM_SMEM (2 * BUF_B)       // 147456

template <int MODE>
__global__ __launch_bounds__(256, 1) void mma_gemm_kernel(
    const __nv_bfloat16* __restrict__ Ahi, const __nv_bfloat16* __restrict__ Alo,
    const __nv_bfloat16* __restrict__ Bhi, const __nv_bfloat16* __restrict__ Blo,
    const float* __restrict__ bias, float* __restrict__ outp)
{
    extern __shared__ char sm[];
    const uint32_t smb = smem_to_u32(sm);
    const int tid = threadIdx.x;
    const int lane = tid & 31;
    const int wid = tid >> 5;
    const int wm = wid & 1;
    const int wn = wid >> 1;
    const int row0 = blockIdx.y * 128;
    const int col0 = blockIdx.x * 128;

    float c[4][4][4];
    #pragma unroll
    for (int i = 0; i < 4; i++)
        #pragma unroll
        for (int j = 0; j < 4; j++)
            #pragma unroll
            for (int e = 0; e < 4; e++) c[i][j][e] = 0.f;

    const int frow = tid >> 3;
    const int fcol = tid & 7;

    const uint32_t offA = (uint32_t)(wm * 64 + (lane & 15)) * 144 + ((lane >> 4) << 3) * 2;
    const uint32_t offB = (uint32_t)(wn * 32 + ((lane >> 4) << 3) + (lane & 7)) * 144 +
                          (((lane >> 3) & 1) << 3) * 2;

    auto prefetch = [&](int kb, int buf) {
        uint32_t sb = smb + buf * BUF_B;
        #pragma unroll
        for (int i = 0; i < 4; i++) {
            int row = frow + 32 * i;
            size_t gA = (size_t)(row0 + row) * PDIM + kb * 64 + fcol * 8;
            size_t gB = (size_t)(col0 + row) * PDIM + kb * 64 + fcol * 8;
            uint32_t so = (uint32_t)row * 144 + fcol * 16;
            cp_async16(sb + 0 * TILE_B + so, Ahi + gA);
            cp_async16(sb + 1 * TILE_B + so, Alo + gA);
            cp_async16(sb + 2 * TILE_B + so, Bhi + gB);
            cp_async16(sb + 3 * TILE_B + so, Blo + gB);
        }
        CP_COMMIT();
    };

    prefetch(0, 0);

    for (int kb = 0; kb < 8; kb++) {
        if (kb + 1 < 8) {
            prefetch(kb + 1, (kb + 1) & 1);
            CP_WAIT(1);
        } else {
            CP_WAIT(0);
        }
        __syncthreads();

        const uint32_t sb = smb + (kb & 1) * BUF_B;
        #pragma unroll
        for (int ks = 0; ks < 4; ks++) {
            uint32_t ah[4][4], al[4][4], bhv[2][4], blv[2][4];
            #pragma unroll
            for (int mf = 0; mf < 4; mf++) {
                ldsm4(ah[mf], sb + 0 * TILE_B + offA + mf * (16 * 144) + ks * 32);
                ldsm4(al[mf], sb + 1 * TILE_B + offA + mf * (16 * 144) + ks * 32);
            }
            #pragma unroll
            for (int nb = 0; nb < 2; nb++) {
                ldsm4(bhv[nb], sb + 2 * TILE_B + offB + nb * (16 * 144) + ks * 32);
                ldsm4(blv[nb], sb + 3 * TILE_B + offB + nb * (16 * 144) + ks * 32);
            }
            #pragma unroll
            for (int mf = 0; mf < 4; mf++) {
                #pragma unroll
                for (int nf = 0; nf < 4; nf++) {
                    const uint32_t* ph = &bhv[nf >> 1][(nf & 1) * 2];
                    const uint32_t* pl = &blv[nf >> 1][(nf & 1) * 2];
                    mma16816(c[mf][nf], ah[mf], ph);
                    mma16816(c[mf][nf], ah[mf], pl);
                    mma16816(c[mf][nf], al[mf], ph);
                }
            }
        }
        __syncthreads();
    }

    float* ts = (float*)sm;
    const int g = lane >> 2, tg = lane & 3;
    #pragma unroll
    for (int mf = 0; mf < 4; mf++) {
        #pragma unroll
        for (int nf = 0; nf < 4; nf++) {
            int r = wm * 64 + mf * 16 + g;
            int cc = wn * 32 + nf * 8 + 2 * tg;
            ts[r * 132 + cc]           = c[mf][nf][0];
            ts[r * 132 + cc + 1]       = c[mf][nf][1];
            ts[(r + 8) * 132 + cc]     = c[mf][nf][2];
            ts[(r + 8) * 132 + cc + 1] = c[mf][nf][3];
        }
    }
    __syncthreads();

    if (MODE == 0) {
        int which = col0 >> 9;
        int c0 = col0 & 511;
        int h0 = c0 >> 6;
        float* dst = which == 0 ? g_q : (which == 1 ? g_k : g_v);
        float scale = which == 0 ? 0.125f : 1.0f;
        #pragma unroll
        for (int t = 0; t < 16; t++) {
            int idx = tid + t * 256;
            int row = idx >> 5;
            int cc = (idx & 31) * 4;
            int m = row0 + row;
            if (m >= PM1) continue;
            int b = m / PN, n = m - b * PN;
            int h = h0 + (cc >> 6), d = cc & 63;
            float4 v = *(float4*)&ts[row * 132 + cc];
            v.x *= scale; v.y *= scale; v.z *= scale; v.w *= scale;
            *(float4*)&dst[(((size_t)(b * PH + h) * PN + n) << 6) + d] = v;
        }
    } else {
        #pragma unroll
        for (int t = 0; t < 16; t++) {
            int idx = tid + t * 256;
            int row = idx >> 5;
            int cc = (idx & 31) * 4;
            int m = row0 + row;
            if (m >= PM1) continue;
            int col = col0 + cc;
            float4 v = *(float4*)&ts[row * 132 + cc];
            float4 bv = *(const float4*)&bias[col];
            v.x += bv.x; v.y += bv.y; v.z += bv.z; v.w += bv.w;
            *(float4*)&outp[(size_t)m * PDIM + col] = v;
        }
    }
}

// -------------------- joints attention ---------------------------------------
#define J1_SMEM (PJ * PDH * 4 + PDH * 257 * 4)   // 71936

__global__ __launch_bounds__(64) void joints_logits_kernel()
{
    extern __shared__ float smf[];
    float* qs  = smf;                 // [24][64]
    float* ksT = smf + PJ * PDH;      // [64][257]

    const int bh = blockIdx.y;
    const int kb = blockIdx.x;
    const int tid = threadIdx.x;
    const int n0 = kb * 256;
    const size_t base = (size_t)bh * PN * PDH;

    #pragma unroll
    for (int i = 0; i < 24; i++)
        qs[tid + 64 * i] = g_q[base + tid + 64 * i];

    #pragma unroll 8
    for (int i = 0; i < 64; i++) {
        int idx = tid + 64 * i;
        int key = idx >> 4;
        int d4 = (idx & 15) << 2;
        int n = n0 + key;
        if (n < PN) {
            float4 v = *(const float4*)&g_k[base + (size_t)n * PDH + d4];
            ksT[(d4 + 0) * 257 + key] = v.x;
            ksT[(d4 + 1) * 257 + key] = v.y;
            ksT[(d4 + 2) * 257 + key] = v.z;
            ksT[(d4 + 3) * 257 + key] = v.w;
        }
    }
    __syncthreads();

    float acc[24][4];
    #pragma unroll
    for (int j = 0; j < 24; j++)
        #pragma unroll
        for (int s = 0; s < 4; s++) acc[j][s] = 0.f;

    for (int d = 0; d < PDH; d++) {
        float k0 = ksT[d * 257 + tid];
        float k1 = ksT[d * 257 + tid + 64];
        float k2 = ksT[d * 257 + tid + 128];
        float k3 = ksT[d * 257 + tid + 192];
        #pragma unroll
        for (int j = 0; j < 24; j++) {
            float qv = qs[j * 64 + d];
            acc[j][0] += qv * k0;
            acc[j][1] += qv * k1;
            acc[j][2] += qv * k2;
            acc[j][3] += qv * k3;
        }
    }

    #pragma unroll
    for (int s = 0; s < 4; s++) {
        int n = n0 + tid + 64 * s;
        if (n < PN) {
            #pragma unroll
            for (int j = 0; j < 24; j++)
                g_jp[((size_t)bh * PJ + j) * PN + n] = __expf(acc[j][s]);
        }
    }
}

#define J2_SMEM (256 * PDH * 4 + PJ * 256 * 4)    // 90112

__global__ __launch_bounds__(256) void joints_pv_kernel()
{
    extern __shared__ float smf[];
    float* vs = smf;                  // [256][64]
    float* ps = smf + 256 * PDH;      // [24][256]

    const int bh = blockIdx.y;
    const int bx = blockIdx.x;
    const int tid = threadIdx.x;
    const int d = tid & 63;
    const int jg = tid >> 6;
    const int n0 = bx * JCHUNK;
    int total = PN - n0; if (total > JCHUNK) total = JCHUNK;
    const size_t base = (size_t)bh * PN * PDH;

    float out[6], psum[6];
    #pragma unroll
    for (int t = 0; t < 6; t++) { out[t] = 0.f; psum[t] = 0.f; }

    for (int c = 0; c < 4; c++) {
        int n0c = n0 + c * 256;
        int cnt = total - c * 256;
        if (cnt <= 0) break;
        if (cnt > 256) cnt = 256;

        #pragma unroll
        for (int t = 0; t < 16; t++) {
            int idx = tid + t * 256;
            int key = idx >> 4;
            int d4 = (idx & 15) << 2;
            float4 v = make_float4(0.f, 0.f, 0.f, 0.f);
            if (key < cnt) v = *(const float4*)&g_v[base + (size_t)(n0c + key) * PDH + d4];
            *(float4*)&vs[key * PDH + d4] = v;
        }
        #pragma unroll
        for (int t = 0; t < 6; t++) {
            int idx = tid + t * 256;
            int j = idx >> 6;
            int nn4 = (idx & 63) << 2;
            float4 v;
            if (nn4 + 3 < cnt) {
                v = *(const float4*)&g_jp[((size_t)bh * PJ + j) * PN + n0c + nn4];
            } else {
                float tmp[4];
                #pragma unroll
                for (int e = 0; e < 4; e++)
                    tmp[e] = (nn4 + e < cnt)
                        ? g_jp[((size_t)bh * PJ + j) * PN + n0c + nn4 + e] : 0.f;
                v = make_float4(tmp[0], tmp[1], tmp[2], tmp[3]);
            }
            *(float4*)&ps[j * 256 + nn4] = v;
        }
        __syncthreads();

        for (int nn = 0; nn < 256; nn += 4) {
            float v0 = vs[(nn + 0) * PDH + d];
            float v1 = vs[(nn + 1) * PDH + d];
            float v2 = vs[(nn + 2) * PDH + d];
            float v3 = vs[(nn + 3) * PDH + d];
            #pragma unroll
            for (int t = 0; t < 6; t++) {
                int j = jg + 4 * t;
                float4 p4 = *(float4*)&ps[j * 256 + nn];
                out[t] += p4.x * v0 + p4.y * v1 + p4.z * v2 + p4.w * v3;
                psum[t] += p4.x + p4.y + p4.z + p4.w;
            }
        }
        __syncthreads();
    }

    #pragma unroll
    for (int t = 0; t < 6; t++) {
        int j = jg + 4 * t;
        g_jout[(((size_t)bx * PBH + bh) * PJ + j) * PDH + d] = out[t];
        if (d == 0) g_jpsum[((size_t)bx * PBH + bh) * PJ + j] = psum[t];
    }
}

__global__ __launch_bounds__(256) void joints_finish_kernel()
{
    const int bh = blockIdx.x;
    const int tid = threadIdx.x;
    const int d = tid & 63;
    const int jg = tid >> 6;
    const int b = bh >> 3, h = bh & 7;
    #pragma unroll
    for (int t = 0; t < 6; t++) {
        int j = jg + 4 * t;
        float o = 0.f, s = 0.f;
        #pragma unroll
        for (int bx = 0; bx < 4; bx++) {
            o += g_jout[(((size_t)bx * PBH + bh) * PJ + j) * PDH + d];
            s += g_jpsum[((size_t)bx * PBH + bh) * PJ + j];
        }
        g_o[((size_t)(b * PN + j)) * (PH * PDH) + h * PDH + d] = o / s;
    }
}

// -------------------- spatial attention (no-max single pass) ------------------
// 256 threads, 1 CTA/SM (full register budget -- no spills). Logits are small
// (q pre-scaled by 0.125), exp without max subtraction is safe; softmax is
// shift-invariant so the result matches the reference.
#define SPATIAL_SMEM (2 * NKEY * PDH * (int)sizeof(float))

__global__ __launch_bounds__(256, 1) void spatial_attn_kernel(
    const float* __restrict__ sinp, const float* __restrict__ cosp)
{
    extern __shared__ float smf[];
    float* ks = smf;
    float* vs = smf + NKEY * PDH;

    const int bh = blockIdx.y;
    const int f  = blockIdx.x;
    const int tid = threadIdx.x;
    const size_t base = (size_t)bh * PN * PDH;

    for (int idx = tid; idx < NKEY * PDH; idx += 256) {
        int nrow = idx >> 6;
        int d = idx & 63;
        int gn = (nrow < PJ) ? nrow : (PJ + f * PNS + (nrow - PJ));
        float kv = g_k[base + (size_t)gn * PDH + d];
        float vv = g_v[base + (size_t)gn * PDH + d];
        if (nrow >= PJ && d < PROT) {
            int s = nrow - PJ;
            float c = cosp[s * PROT + d];
            float sn = sinp[s * PROT + d];
            float partner = g_k[base + (size_t)gn * PDH + (d ^ 1)];
            kv = (d & 1) ? (kv * c + partner * sn) : (kv * c - partner * sn);
        }
        ks[idx] = kv;
        vs[idx] = vv;
    }
    __syncthreads();

    if (tid < PNS) {
        const int s = tid;
        const int gn = PJ + f * PNS + s;
        float qr[PDH];
        const float* qp = g_q + base + (size_t)gn * PDH;
        #pragma unroll
        for (int d = 0; d < PDH; d++) qr[d] = qp[d];
        #pragma unroll
        for (int d = 0; d < PROT; d += 2) {
            float c0 = cosp[s * PROT + d],     s0 = sinp[s * PROT + d];
            float c1 = cosp[s * PROT + d + 1], s1 = sinp[s * PROT + d + 1];
            float a = qr[d], b2 = qr[d + 1];
            qr[d]     = a * c0 - b2 * s0;
            qr[d + 1] = b2 * c1 + a * s1;
        }

        float l = 0.f;
        float out[PDH];
        #pragma unroll
        for (int d = 0; d < PDH; d++) out[d] = 0.f;

        for (int n = 0; n < NKEY; n++) {
            float dot = 0.f;
            #pragma unroll
            for (int d = 0; d < PDH; d++) dot += qr[d] * ks[n * PDH + d];
            float p = __expf(dot);
            l += p;
            #pragma unroll
            for (int d = 0; d < PDH; d++) out[d] += p * vs[n * PDH + d];
        }

        const float inv = 1.f / l;
        const int b = bh >> 3, h = bh & 7;
        float* op = g_o + ((size_t)(b * PN + gn)) * (PH * PDH) + h * PDH;
        #pragma unroll
        for (int d = 0; d < PDH; d++) op[d] = out[d] * inv;
    }
}

// -------------------- launch --------------------------------------------------
extern "C" void kernel_launch(void* const* d_in, const int* in_sizes, int n_in,
                              void* d_out, int out_size)
{
    (void)in_sizes; (void)n_in; (void)out_size;
    const float* x      = (const float*)d_in[0];
    const float* w_qkv  = (const float*)d_in[1];
    const float* w_out  = (const float*)d_in[2];
    const float* b_out  = (const float*)d_in[3];
    const float* sinp   = (const float*)d_in[4];
    const float* cosp   = (const float*)d_in[5];
    float* out = (float*)d_out;

    cudaFuncSetAttribute(spatial_attn_kernel,
                         cudaFuncAttributeMaxDynamicSharedMemorySize, SPATIAL_SMEM);
    cudaFuncSetAttribute(mma_gemm_kernel<0>,
                         cudaFuncAttributeMaxDynamicSharedMemorySize, GEMM_SMEM);
    cudaFuncSetAttribute(mma_gemm_kernel<1>,
                         cudaFuncAttributeMaxDynamicSharedMemorySize, GEMM_SMEM);
    cudaFuncSetAttribute(joints_logits_kernel,
                         cudaFuncAttributeMaxDynamicSharedMemorySize, J1_SMEM);
    cudaFuncSetAttribute(joints_pv_kernel,
                         cudaFuncAttributeMaxDynamicSharedMemorySize, J2_SMEM);

    __nv_bfloat16 *xhi, *xlo, *ohi, *olo, *wqh, *wql, *woh, *wol;
    cudaGetSymbolAddress((void**)&xhi, g_xhi);
    cudaGetSymbolAddress((void**)&xlo, g_xlo);
    cudaGetSymbolAddress((void**)&ohi, g_ohi);
    cudaGetSymbolAddress((void**)&olo, g_olo);
    cudaGetSymbolAddress((void**)&wqh, g_wqkvT_hi);
    cudaGetSymbolAddress((void**)&wql, g_wqkvT_lo);
    cudaGetSymbolAddress((void**)&woh, g_woutT_hi);
    cudaGetSymbolAddress((void**)&wol, g_woutT_lo);

    // 1) split-convert x and transpose-convert weights
    {
        int n4 = PM1 * PDIM / 4;
        convert_split_kernel<<<(n4 + 255) / 256, 256>>>(x, xhi, xlo, n4);
        int nw = PDIM * NQKV;
        convert_wT_kernel<<<(nw + 255) / 256, 256>>>(w_qkv, wqh, wql, PDIM, NQKV);
        int nw2 = PDIM * PDIM;
        convert_wT_kernel<<<(nw2 + 255) / 256, 256>>>(w_out, woh, wol, PDIM, PDIM);
    }

    // 2) QKV projection (tensor cores, cp.async double-buffered)
    mma_gemm_kernel<0><<<dim3(NQKV / 128, (PM1 + 127) / 128), 256, GEMM_SMEM>>>(
        xhi, xlo, wqh, wql, nullptr, nullptr);

    // 3) joints attention
    joints_logits_kernel<<<dim3((PN + 255) / 256, PBH), 64, J1_SMEM>>>();
    joints_pv_kernel<<<dim3(4, PBH), 256, J2_SMEM>>>();
    joints_finish_kernel<<<PBH, 256>>>();

    // 4) spatial attention (no-max single pass, full register budget)
    spatial_attn_kernel<<<dim3(PF, PBH), 256, SPATIAL_SMEM>>>(sinp, cosp);

    // 5) output projection + bias
    {
        int n4 = PM1 * PDIM / 4;
        const float* gop;
        cudaGetSymbolAddress((void**)&gop, g_o);
        convert_split_kernel<<<(n4 + 255) / 256, 256>>>(gop, ohi, olo, n4);
    }
    mma_gemm_kernel<1><<<dim3(PDIM / 128, (PM1 + 127) / 128), 256, GEMM_SMEM>>>(
        ohi, olo, woh, wol, b_out, out);
}

// round 13
// speedup vs baseline: 1.5707x; 1.5707x over previous
#include <cuda_runtime.h>
#include <cuda_bf16.h>
#include <math.h>
#include <stdint.h>

// Problem constants
#define PB   8
#define PF   16
#define PNS  196
#define PJ   24
#define PH   8
#define PDH  64
#define PDIM 512
#define PROT 32
#define PN   (PJ + PF * PNS)   // 3160
#define PBH  (PB * PH)         // 64
#define PM1  (PB * PN)         // 25280
#define NKEY (PJ + PNS)        // 220
#define NQKV (3 * PDIM)        // 1536

// -------------------- scratch (device globals) ------------------------------
__device__ __align__(16) float g_q[(size_t)PBH * PN * PDH];
__device__ __align__(16) float g_k[(size_t)PBH * PN * PDH];
__device__ __align__(16) float g_v[(size_t)PBH * PN * PDH];

__device__ __align__(16) __nv_bfloat16 g_xhi[(size_t)(PM1 + 128) * PDIM];
__device__ __align__(16) __nv_bfloat16 g_xlo[(size_t)(PM1 + 128) * PDIM];
__device__ __align__(16) __nv_bfloat16 g_ohi[(size_t)(PM1 + 128) * PDIM];
__device__ __align__(16) __nv_bfloat16 g_olo[(size_t)(PM1 + 128) * PDIM];
__device__ __align__(16) __nv_bfloat16 g_wqkvT_hi[(size_t)NQKV * PDIM];  // [N][K]
__device__ __align__(16) __nv_bfloat16 g_wqkvT_lo[(size_t)NQKV * PDIM];
__device__ __align__(16) __nv_bfloat16 g_woutT_hi[(size_t)PDIM * PDIM];  // [N][K]
__device__ __align__(16) __nv_bfloat16 g_woutT_lo[(size_t)PDIM * PDIM];

// joints attention scratch
__device__ __align__(16) float g_jp[(size_t)PBH * PJ * PN];
__device__ __align__(16) float g_jout[4 * PBH * PJ * PDH];
__device__ __align__(16) float g_jpsum[4 * PBH * PJ];

#define JCHUNK 792

// -------------------- asm helpers -------------------------------------------
__device__ __forceinline__ uint32_t smem_to_u32(const void* p) {
    uint32_t a;
    asm("{ .reg .u64 t; cvta.to.shared.u64 t, %1; cvt.u32.u64 %0, t; }" : "=r"(a) : "l"(p));
    return a;
}
__device__ __forceinline__ void ldsm4(uint32_t* r, uint32_t addr) {
    asm volatile("ldmatrix.sync.aligned.m8n8.x4.shared.b16 {%0,%1,%2,%3}, [%4];"
        : "=r"(r[0]), "=r"(r[1]), "=r"(r[2]), "=r"(r[3]) : "r"(addr));
}
__device__ __forceinline__ void mma16816(float* c, const uint32_t* a, const uint32_t* b) {
    asm volatile("mma.sync.aligned.m16n8k16.row.col.f32.bf16.bf16.f32 "
        "{%0,%1,%2,%3}, {%4,%5,%6,%7}, {%8,%9}, {%0,%1,%2,%3};"
        : "+f"(c[0]), "+f"(c[1]), "+f"(c[2]), "+f"(c[3])
        : "r"(a[0]), "r"(a[1]), "r"(a[2]), "r"(a[3]), "r"(b[0]), "r"(b[1]));
}
__device__ __forceinline__ void cp_async16(uint32_t saddr, const void* gptr) {
    asm volatile("cp.async.cg.shared.global [%0], [%1], 16;"
        :: "r"(saddr), "l"(gptr) : "memory");
}
#define CP_COMMIT() asm volatile("cp.async.commit_group;" ::: "memory")
#define CP_WAIT(N)  asm volatile("cp.async.wait_group %0;" :: "n"(N) : "memory")

// split a float into bf16 hi + lo
__device__ __forceinline__ void bf_split(float v, __nv_bfloat16& h, __nv_bfloat16& l) {
    h = __float2bfloat16(v);
    l = __float2bfloat16(v - __bfloat162float(h));
}

// -------------------- conversion kernels ------------------------------------
__global__ void convert_split_kernel(const float* __restrict__ src,
                                     __nv_bfloat16* __restrict__ hi,
                                     __nv_bfloat16* __restrict__ lo, int n4) {
    int i = blockIdx.x * blockDim.x + threadIdx.x;
    if (i >= n4) return;
    float4 v = ((const float4*)src)[i];
    __nv_bfloat16 h0, h1, h2, h3, l0, l1, l2, l3;
    bf_split(v.x, h0, l0); bf_split(v.y, h1, l1);
    bf_split(v.z, h2, l2); bf_split(v.w, h3, l3);
    hi[4 * i + 0] = h0; hi[4 * i + 1] = h1; hi[4 * i + 2] = h2; hi[4 * i + 3] = h3;
    lo[4 * i + 0] = l0; lo[4 * i + 1] = l1; lo[4 * i + 2] = l2; lo[4 * i + 3] = l3;
}

__global__ void convert_wT_kernel(const float* __restrict__ w,
                                  __nv_bfloat16* __restrict__ hi,
                                  __nv_bfloat16* __restrict__ lo, int K, int Nn) {
    int i = blockIdx.x * blockDim.x + threadIdx.x;
    if (i >= K * Nn) return;
    int n = i / K, k = i - n * K;
    float v = w[(size_t)k * Nn + n];
    __nv_bfloat16 h, l;
    bf_split(v, h, l);
    hi[i] = h; lo[i] = l;
}

// -------------------- mma.sync split-bf16 GEMM (double-buffered) -------------
#define TILE_B   (128 * 144)        // 18432 bytes per operand tile
#define BUF_B    (4 * TILE_B)       // 73728 per stage
#define GEMM_SMEM (2 * BUF_B)       // 147456

template <int MODE>
__global__ __launch_bounds__(256, 1) void mma_gemm_kernel(
    const __nv_bfloat16* __restrict__ Ahi, const __nv_bfloat16* __restrict__ Alo,
    const __nv_bfloat16* __restrict__ Bhi, const __nv_bfloat16* __restrict__ Blo,
    const float* __restrict__ bias, float* __restrict__ outp)
{
    extern __shared__ char sm[];
    const uint32_t smb = smem_to_u32(sm);
    const int tid = threadIdx.x;
    const int lane = tid & 31;
    const int wid = tid >> 5;
    const int wm = wid & 1;
    const int wn = wid >> 1;
    const int row0 = blockIdx.y * 128;
    const int col0 = blockIdx.x * 128;

    float c[4][4][4];
    #pragma unroll
    for (int i = 0; i < 4; i++)
        #pragma unroll
        for (int j = 0; j < 4; j++)
            #pragma unroll
            for (int e = 0; e < 4; e++) c[i][j][e] = 0.f;

    const int frow = tid >> 3;
    const int fcol = tid & 7;

    const uint32_t offA = (uint32_t)(wm * 64 + (lane & 15)) * 144 + ((lane >> 4) << 3) * 2;
    const uint32_t offB = (uint32_t)(wn * 32 + ((lane >> 4) << 3) + (lane & 7)) * 144 +
                          (((lane >> 3) & 1) << 3) * 2;

    auto prefetch = [&](int kb, int buf) {
        uint32_t sb = smb + buf * BUF_B;
        #pragma unroll
        for (int i = 0; i < 4; i++) {
            int row = frow + 32 * i;
            size_t gA = (size_t)(row0 + row) * PDIM + kb * 64 + fcol * 8;
            size_t gB = (size_t)(col0 + row) * PDIM + kb * 64 + fcol * 8;
            uint32_t so = (uint32_t)row * 144 + fcol * 16;
            cp_async16(sb + 0 * TILE_B + so, Ahi + gA);
            cp_async16(sb + 1 * TILE_B + so, Alo + gA);
            cp_async16(sb + 2 * TILE_B + so, Bhi + gB);
            cp_async16(sb + 3 * TILE_B + so, Blo + gB);
        }
        CP_COMMIT();
    };

    prefetch(0, 0);

    for (int kb = 0; kb < 8; kb++) {
        if (kb + 1 < 8) {
            prefetch(kb + 1, (kb + 1) & 1);
            CP_WAIT(1);
        } else {
            CP_WAIT(0);
        }
        __syncthreads();

        const uint32_t sb = smb + (kb & 1) * BUF_B;
        #pragma unroll
        for (int ks = 0; ks < 4; ks++) {
            uint32_t ah[4][4], al[4][4], bhv[2][4], blv[2][4];
            #pragma unroll
            for (int mf = 0; mf < 4; mf++) {
                ldsm4(ah[mf], sb + 0 * TILE_B + offA + mf * (16 * 144) + ks * 32);
                ldsm4(al[mf], sb + 1 * TILE_B + offA + mf * (16 * 144) + ks * 32);
            }
            #pragma unroll
            for (int nb = 0; nb < 2; nb++) {
                ldsm4(bhv[nb], sb + 2 * TILE_B + offB + nb * (16 * 144) + ks * 32);
                ldsm4(blv[nb], sb + 3 * TILE_B + offB + nb * (16 * 144) + ks * 32);
            }
            #pragma unroll
            for (int mf = 0; mf < 4; mf++) {
                #pragma unroll
                for (int nf = 0; nf < 4; nf++) {
                    const uint32_t* ph = &bhv[nf >> 1][(nf & 1) * 2];
                    const uint32_t* pl = &blv[nf >> 1][(nf & 1) * 2];
                    mma16816(c[mf][nf], ah[mf], ph);
                    mma16816(c[mf][nf], ah[mf], pl);
                    mma16816(c[mf][nf], al[mf], ph);
                }
            }
        }
        __syncthreads();
    }

    float* ts = (float*)sm;
    const int g = lane >> 2, tg = lane & 3;
    #pragma unroll
    for (int mf = 0; mf < 4; mf++) {
        #pragma unroll
        for (int nf = 0; nf < 4; nf++) {
            int r = wm * 64 + mf * 16 + g;
            int cc = wn * 32 + nf * 8 + 2 * tg;
            ts[r * 132 + cc]           = c[mf][nf][0];
            ts[r * 132 + cc + 1]       = c[mf][nf][1];
            ts[(r + 8) * 132 + cc]     = c[mf][nf][2];
            ts[(r + 8) * 132 + cc + 1] = c[mf][nf][3];
        }
    }
    __syncthreads();

    if (MODE == 0) {
        int which = col0 >> 9;
        int c0 = col0 & 511;
        int h0 = c0 >> 6;
        float* dst = which == 0 ? g_q : (which == 1 ? g_k : g_v);
        float scale = which == 0 ? 0.125f : 1.0f;
        #pragma unroll
        for (int t = 0; t < 16; t++) {
            int idx = tid + t * 256;
            int row = idx >> 5;
            int cc = (idx & 31) * 4;
            int m = row0 + row;
            if (m >= PM1) continue;
            int b = m / PN, n = m - b * PN;
            int h = h0 + (cc >> 6), d = cc & 63;
            float4 v = *(float4*)&ts[row * 132 + cc];
            v.x *= scale; v.y *= scale; v.z *= scale; v.w *= scale;
            *(float4*)&dst[(((size_t)(b * PH + h) * PN + n) << 6) + d] = v;
        }
    } else {
        #pragma unroll
        for (int t = 0; t < 16; t++) {
            int idx = tid + t * 256;
            int row = idx >> 5;
            int cc = (idx & 31) * 4;
            int m = row0 + row;
            if (m >= PM1) continue;
            int col = col0 + cc;
            float4 v = *(float4*)&ts[row * 132 + cc];
            float4 bv = *(const float4*)&bias[col];
            v.x += bv.x; v.y += bv.y; v.z += bv.z; v.w += bv.w;
            *(float4*)&outp[(size_t)m * PDIM + col] = v;
        }
    }
}

// -------------------- joints attention ---------------------------------------
#define J1_SMEM (PJ * PDH * 4 + PDH * 257 * 4)   // 71936

__global__ __launch_bounds__(64) void joints_logits_kernel()
{
    extern __shared__ float smf[];
    float* qs  = smf;                 // [24][64]
    float* ksT = smf + PJ * PDH;      // [64][257]

    const int bh = blockIdx.y;
    const int kb = blockIdx.x;
    const int tid = threadIdx.x;
    const int n0 = kb * 256;
    const size_t base = (size_t)bh * PN * PDH;

    #pragma unroll
    for (int i = 0; i < 24; i++)
        qs[tid + 64 * i] = g_q[base + tid + 64 * i];

    #pragma unroll 8
    for (int i = 0; i < 64; i++) {
        int idx = tid + 64 * i;
        int key = idx >> 4;
        int d4 = (idx & 15) << 2;
        int n = n0 + key;
        if (n < PN) {
            float4 v = *(const float4*)&g_k[base + (size_t)n * PDH + d4];
            ksT[(d4 + 0) * 257 + key] = v.x;
            ksT[(d4 + 1) * 257 + key] = v.y;
            ksT[(d4 + 2) * 257 + key] = v.z;
            ksT[(d4 + 3) * 257 + key] = v.w;
        }
    }
    __syncthreads();

    float acc[24][4];
    #pragma unroll
    for (int j = 0; j < 24; j++)
        #pragma unroll
        for (int s = 0; s < 4; s++) acc[j][s] = 0.f;

    for (int d = 0; d < PDH; d++) {
        float k0 = ksT[d * 257 + tid];
        float k1 = ksT[d * 257 + tid + 64];
        float k2 = ksT[d * 257 + tid + 128];
        float k3 = ksT[d * 257 + tid + 192];
        #pragma unroll
        for (int j = 0; j < 24; j++) {
            float qv = qs[j * 64 + d];
            acc[j][0] += qv * k0;
            acc[j][1] += qv * k1;
            acc[j][2] += qv * k2;
            acc[j][3] += qv * k3;
        }
    }

    #pragma unroll
    for (int s = 0; s < 4; s++) {
        int n = n0 + tid + 64 * s;
        if (n < PN) {
            #pragma unroll
            for (int j = 0; j < 24; j++)
                g_jp[((size_t)bh * PJ + j) * PN + n] = __expf(acc[j][s]);
        }
    }
}

#define J2_SMEM (256 * PDH * 4 + PJ * 256 * 4)    // 90112

__global__ __launch_bounds__(256) void joints_pv_kernel()
{
    extern __shared__ float smf[];
    float* vs = smf;                  // [256][64]
    float* ps = smf + 256 * PDH;      // [24][256]

    const int bh = blockIdx.y;
    const int bx = blockIdx.x;
    const int tid = threadIdx.x;
    const int d = tid & 63;
    const int jg = tid >> 6;
    const int n0 = bx * JCHUNK;
    int total = PN - n0; if (total > JCHUNK) total = JCHUNK;
    const size_t base = (size_t)bh * PN * PDH;

    float out[6], psum[6];
    #pragma unroll
    for (int t = 0; t < 6; t++) { out[t] = 0.f; psum[t] = 0.f; }

    for (int c = 0; c < 4; c++) {
        int n0c = n0 + c * 256;
        int cnt = total - c * 256;
        if (cnt <= 0) break;
        if (cnt > 256) cnt = 256;

        #pragma unroll
        for (int t = 0; t < 16; t++) {
            int idx = tid + t * 256;
            int key = idx >> 4;
            int d4 = (idx & 15) << 2;
            float4 v = make_float4(0.f, 0.f, 0.f, 0.f);
            if (key < cnt) v = *(const float4*)&g_v[base + (size_t)(n0c + key) * PDH + d4];
            *(float4*)&vs[key * PDH + d4] = v;
        }
        #pragma unroll
        for (int t = 0; t < 6; t++) {
            int idx = tid + t * 256;
            int j = idx >> 6;
            int nn4 = (idx & 63) << 2;
            float4 v;
            if (nn4 + 3 < cnt) {
                v = *(const float4*)&g_jp[((size_t)bh * PJ + j) * PN + n0c + nn4];
            } else {
                float tmp[4];
                #pragma unroll
                for (int e = 0; e < 4; e++)
                    tmp[e] = (nn4 + e < cnt)
                        ? g_jp[((size_t)bh * PJ + j) * PN + n0c + nn4 + e] : 0.f;
                v = make_float4(tmp[0], tmp[1], tmp[2], tmp[3]);
            }
            *(float4*)&ps[j * 256 + nn4] = v;
        }
        __syncthreads();

        for (int nn = 0; nn < 256; nn += 4) {
            float v0 = vs[(nn + 0) * PDH + d];
            float v1 = vs[(nn + 1) * PDH + d];
            float v2 = vs[(nn + 2) * PDH + d];
            float v3 = vs[(nn + 3) * PDH + d];
            #pragma unroll
            for (int t = 0; t < 6; t++) {
                int j = jg + 4 * t;
                float4 p4 = *(float4*)&ps[j * 256 + nn];
                out[t] += p4.x * v0 + p4.y * v1 + p4.z * v2 + p4.w * v3;
                psum[t] += p4.x + p4.y + p4.z + p4.w;
            }
        }
        __syncthreads();
    }

    #pragma unroll
    for (int t = 0; t < 6; t++) {
        int j = jg + 4 * t;
        g_jout[(((size_t)bx * PBH + bh) * PJ + j) * PDH + d] = out[t];
        if (d == 0) g_jpsum[((size_t)bx * PBH + bh) * PJ + j] = psum[t];
    }
}

// J3: combine partials, divide, write bf16 hi/lo directly
__global__ __launch_bounds__(256) void joints_finish_kernel()
{
    const int bh = blockIdx.x;
    const int tid = threadIdx.x;
    const int d = tid & 63;
    const int jg = tid >> 6;
    const int b = bh >> 3, h = bh & 7;
    #pragma unroll
    for (int t = 0; t < 6; t++) {
        int j = jg + 4 * t;
        float o = 0.f, s = 0.f;
        #pragma unroll
        for (int bx = 0; bx < 4; bx++) {
            o += g_jout[(((size_t)bx * PBH + bh) * PJ + j) * PDH + d];
            s += g_jpsum[((size_t)bx * PBH + bh) * PJ + j];
        }
        float v = o / s;
        size_t off = (size_t)(b * PN + j) * PDIM + h * PDH + d;
        __nv_bfloat16 hh, ll;
        bf_split(v, hh, ll);
        g_ohi[off] = hh;
        g_olo[off] = ll;
    }
}

// -------------------- spatial attention (no-max single pass, float4) ----------
// 256 threads, 1 CTA/SM. exp without max subtraction is safe (logits small);
// epilogue writes bf16 hi/lo directly (no separate conversion pass).
#define SPATIAL_SMEM (2 * NKEY * PDH * (int)sizeof(float))

__global__ __launch_bounds__(256, 1) void spatial_attn_kernel(
    const float* __restrict__ sinp, const float* __restrict__ cosp)
{
    extern __shared__ float smf[];
    float* ks = smf;
    float* vs = smf + NKEY * PDH;

    const int bh = blockIdx.y;
    const int f  = blockIdx.x;
    const int tid = threadIdx.x;
    const size_t base = (size_t)bh * PN * PDH;

    for (int idx = tid; idx < NKEY * PDH; idx += 256) {
        int nrow = idx >> 6;
        int d = idx & 63;
        int gn = (nrow < PJ) ? nrow : (PJ + f * PNS + (nrow - PJ));
        float kv = g_k[base + (size_t)gn * PDH + d];
        float vv = g_v[base + (size_t)gn * PDH + d];
        if (nrow >= PJ && d < PROT) {
            int s = nrow - PJ;
            float c = cosp[s * PROT + d];
            float sn = sinp[s * PROT + d];
            float partner = g_k[base + (size_t)gn * PDH + (d ^ 1)];
            kv = (d & 1) ? (kv * c + partner * sn) : (kv * c - partner * sn);
        }
        ks[idx] = kv;
        vs[idx] = vv;
    }
    __syncthreads();

    if (tid < PNS) {
        const int s = tid;
        const int gn = PJ + f * PNS + s;

        float4 q4[16];
        const float4* qp = (const float4*)(g_q + base + (size_t)gn * PDH);
        #pragma unroll
        for (int i = 0; i < 16; i++) q4[i] = qp[i];

        // RoPE on first 32 dims (8 float4 groups; pairs (x,y) and (z,w))
        #pragma unroll
        for (int i = 0; i < 8; i++) {
            int d0 = 4 * i;
            float c0 = cosp[s * PROT + d0],     s0 = sinp[s * PROT + d0];
            float c1 = cosp[s * PROT + d0 + 1], s1 = sinp[s * PROT + d0 + 1];
            float c2 = cosp[s * PROT + d0 + 2], s2 = sinp[s * PROT + d0 + 2];
            float c3 = cosp[s * PROT + d0 + 3], s3 = sinp[s * PROT + d0 + 3];
            float ax = q4[i].x, ay = q4[i].y, az = q4[i].z, aw = q4[i].w;
            q4[i].x = ax * c0 - ay * s0;
            q4[i].y = ay * c1 + ax * s1;
            q4[i].z = az * c2 - aw * s2;
            q4[i].w = aw * c3 + az * s3;
        }

        float l = 0.f;
        float4 o4[16];
        #pragma unroll
        for (int i = 0; i < 16; i++) o4[i] = make_float4(0.f, 0.f, 0.f, 0.f);

        for (int n = 0; n < NKEY; n++) {
            const float4* kp = (const float4*)&ks[n * PDH];
            float dot = 0.f;
            #pragma unroll
            for (int i = 0; i < 16; i++) {
                float4 kv = kp[i];
                dot += q4[i].x * kv.x + q4[i].y * kv.y + q4[i].z * kv.z + q4[i].w * kv.w;
            }
            float p = __expf(dot);
            l += p;
            const float4* vp = (const float4*)&vs[n * PDH];
            #pragma unroll
            for (int i = 0; i < 16; i++) {
                float4 vv = vp[i];
                o4[i].x += p * vv.x; o4[i].y += p * vv.y;
                o4[i].z += p * vv.z; o4[i].w += p * vv.w;
            }
        }

        const float inv = 1.f / l;
        const int b = bh >> 3, h = bh & 7;
        size_t off = (size_t)(b * PN + gn) * PDIM + h * PDH;
        __nv_bfloat16* ohp = g_ohi + off;
        __nv_bfloat16* olp = g_olo + off;
        #pragma unroll
        for (int i = 0; i < 16; i++) {
            float vals[4] = {o4[i].x * inv, o4[i].y * inv, o4[i].z * inv, o4[i].w * inv};
            __nv_bfloat16 hh[4], ll[4];
            #pragma unroll
            for (int e = 0; e < 4; e++) bf_split(vals[e], hh[e], ll[e]);
            #pragma unroll
            for (int e = 0; e < 4; e++) { ohp[4 * i + e] = hh[e]; olp[4 * i + e] = ll[e]; }
        }
    }
}

// -------------------- launch --------------------------------------------------
extern "C" void kernel_launch(void* const* d_in, const int* in_sizes, int n_in,
                              void* d_out, int out_size)
{
    (void)in_sizes; (void)n_in; (void)out_size;
    const float* x      = (const float*)d_in[0];
    const float* w_qkv  = (const float*)d_in[1];
    const float* w_out  = (const float*)d_in[2];
    const float* b_out  = (const float*)d_in[3];
    const float* sinp   = (const float*)d_in[4];
    const float* cosp   = (const float*)d_in[5];
    float* out = (float*)d_out;

    cudaFuncSetAttribute(spatial_attn_kernel,
                         cudaFuncAttributeMaxDynamicSharedMemorySize, SPATIAL_SMEM);
    cudaFuncSetAttribute(mma_gemm_kernel<0>,
                         cudaFuncAttributeMaxDynamicSharedMemorySize, GEMM_SMEM);
    cudaFuncSetAttribute(mma_gemm_kernel<1>,
                         cudaFuncAttributeMaxDynamicSharedMemorySize, GEMM_SMEM);
    cudaFuncSetAttribute(joints_logits_kernel,
                         cudaFuncAttributeMaxDynamicSharedMemorySize, J1_SMEM);
    cudaFuncSetAttribute(joints_pv_kernel,
                         cudaFuncAttributeMaxDynamicSharedMemorySize, J2_SMEM);

    __nv_bfloat16 *xhi, *xlo, *ohi, *olo, *wqh, *wql, *woh, *wol;
    cudaGetSymbolAddress((void**)&xhi, g_xhi);
    cudaGetSymbolAddress((void**)&xlo, g_xlo);
    cudaGetSymbolAddress((void**)&ohi, g_ohi);
    cudaGetSymbolAddress((void**)&olo, g_olo);
    cudaGetSymbolAddress((void**)&wqh, g_wqkvT_hi);
    cudaGetSymbolAddress((void**)&wql, g_wqkvT_lo);
    cudaGetSymbolAddress((void**)&woh, g_woutT_hi);
    cudaGetSymbolAddress((void**)&wol, g_woutT_lo);

    // 1) split-convert x and transpose-convert weights
    {
        int n4 = PM1 * PDIM / 4;
        convert_split_kernel<<<(n4 + 255) / 256, 256>>>(x, xhi, xlo, n4);
        int nw = PDIM * NQKV;
        convert_wT_kernel<<<(nw + 255) / 256, 256>>>(w_qkv, wqh, wql, PDIM, NQKV);
        int nw2 = PDIM * PDIM;
        convert_wT_kernel<<<(nw2 + 255) / 256, 256>>>(w_out, woh, wol, PDIM, PDIM);
    }

    // 2) QKV projection (tensor cores, cp.async double-buffered)
    mma_gemm_kernel<0><<<dim3(NQKV / 128, (PM1 + 127) / 128), 256, GEMM_SMEM>>>(
        xhi, xlo, wqh, wql, nullptr, nullptr);

    // 3) joints attention (writes g_ohi/g_olo rows n<24 directly)
    joints_logits_kernel<<<dim3((PN + 255) / 256, PBH), 64, J1_SMEM>>>();
    joints_pv_kernel<<<dim3(4, PBH), 256, J2_SMEM>>>();
    joints_finish_kernel<<<PBH, 256>>>();

    // 4) spatial attention (writes g_ohi/g_olo rows n>=24 directly)
    spatial_attn_kernel<<<dim3(PF, PBH), 256, SPATIAL_SMEM>>>(sinp, cosp);

    // 5) output projection + bias (consumes g_ohi/g_olo directly)
    mma_gemm_kernel<1><<<dim3(PDIM / 128, (PM1 + 127) / 128), 256, GEMM_SMEM>>>(
        ohi, olo, woh, wol, b_out, out);
}

// round 15
// speedup vs baseline: 1.5767x; 1.0038x over previous
#include <cuda_runtime.h>
#include <cuda_bf16.h>
#include <math.h>
#include <stdint.h>

// Problem constants
#define PB   8
#define PF   16
#define PNS  196
#define PJ   24
#define PH   8
#define PDH  64
#define PDIM 512
#define PROT 32
#define PN   (PJ + PF * PNS)   // 3160
#define PBH  (PB * PH)         // 64
#define PM1  (PB * PN)         // 25280
#define NKEY (PJ + PNS)        // 220
#define NQKV (3 * PDIM)        // 1536

// -------------------- scratch (device globals) ------------------------------
__device__ __align__(16) float g_q[(size_t)PBH * PN * PDH];
__device__ __align__(16) float g_k[(size_t)PBH * PN * PDH];
__device__ __align__(16) float g_v[(size_t)PBH * PN * PDH];

__device__ __align__(16) __nv_bfloat16 g_xhi[(size_t)(PM1 + 128) * PDIM];
__device__ __align__(16) __nv_bfloat16 g_xlo[(size_t)(PM1 + 128) * PDIM];
__device__ __align__(16) __nv_bfloat16 g_ohi[(size_t)(PM1 + 128) * PDIM];
__device__ __align__(16) __nv_bfloat16 g_olo[(size_t)(PM1 + 128) * PDIM];
__device__ __align__(16) __nv_bfloat16 g_wqkvT_hi[(size_t)NQKV * PDIM];  // [N][K]
__device__ __align__(16) __nv_bfloat16 g_wqkvT_lo[(size_t)NQKV * PDIM];
__device__ __align__(16) __nv_bfloat16 g_woutT_hi[(size_t)PDIM * PDIM];  // [N][K]
__device__ __align__(16) __nv_bfloat16 g_woutT_lo[(size_t)PDIM * PDIM];

// joints attention scratch
__device__ __align__(16) float g_jp[(size_t)PBH * PJ * PN];
__device__ __align__(16) float g_jout[4 * PBH * PJ * PDH];
__device__ __align__(16) float g_jpsum[4 * PBH * PJ];

#define JCHUNK 792

// -------------------- asm helpers -------------------------------------------
__device__ __forceinline__ uint32_t smem_to_u32(const void* p) {
    uint32_t a;
    asm("{ .reg .u64 t; cvta.to.shared.u64 t, %1; cvt.u32.u64 %0, t; }" : "=r"(a) : "l"(p));
    return a;
}
__device__ __forceinline__ void ldsm4(uint32_t* r, uint32_t addr) {
    asm volatile("ldmatrix.sync.aligned.m8n8.x4.shared.b16 {%0,%1,%2,%3}, [%4];"
        : "=r"(r[0]), "=r"(r[1]), "=r"(r[2]), "=r"(r[3]) : "r"(addr));
}
__device__ __forceinline__ void mma16816(float* c, const uint32_t* a, const uint32_t* b) {
    asm volatile("mma.sync.aligned.m16n8k16.row.col.f32.bf16.bf16.f32 "
        "{%0,%1,%2,%3}, {%4,%5,%6,%7}, {%8,%9}, {%0,%1,%2,%3};"
        : "+f"(c[0]), "+f"(c[1]), "+f"(c[2]), "+f"(c[3])
        : "r"(a[0]), "r"(a[1]), "r"(a[2]), "r"(a[3]), "r"(b[0]), "r"(b[1]));
}
__device__ __forceinline__ void cp_async16(uint32_t saddr, const void* gptr) {
    asm volatile("cp.async.cg.shared.global [%0], [%1], 16;"
        :: "r"(saddr), "l"(gptr) : "memory");
}
#define CP_COMMIT() asm volatile("cp.async.commit_group;" ::: "memory")
#define CP_WAIT(N)  asm volatile("cp.async.wait_group %0;" :: "n"(N) : "memory")

// packed fp32x2 FMA (Blackwell FFMA2; PTX-only path)
__device__ __forceinline__ void ffma2(uint64_t& d, uint64_t a, uint64_t b) {
    asm("fma.rn.f32x2 %0, %1, %2, %0;" : "+l"(d) : "l"(a), "l"(b));
}
__device__ __forceinline__ uint64_t pk2(float lo, float hi) {
    uint64_t r; asm("mov.b64 %0, {%1, %2};" : "=l"(r) : "f"(lo), "f"(hi)); return r;
}
__device__ __forceinline__ void upk2(uint64_t v, float& lo, float& hi) {
    asm("mov.b64 {%0, %1}, %2;" : "=f"(lo), "=f"(hi) : "l"(v));
}

// split a float into bf16 hi + lo
__device__ __forceinline__ void bf_split(float v, __nv_bfloat16& h, __nv_bfloat16& l) {
    h = __float2bfloat16(v);
    l = __float2bfloat16(v - __bfloat162float(h));
}

// -------------------- conversion kernels ------------------------------------
__global__ void convert_split_kernel(const float* __restrict__ src,
                                     __nv_bfloat16* __restrict__ hi,
                                     __nv_bfloat16* __restrict__ lo, int n4) {
    int i = blockIdx.x * blockDim.x + threadIdx.x;
    if (i >= n4) return;
    float4 v = ((const float4*)src)[i];
    __nv_bfloat16 h0, h1, h2, h3, l0, l1, l2, l3;
    bf_split(v.x, h0, l0); bf_split(v.y, h1, l1);
    bf_split(v.z, h2, l2); bf_split(v.w, h3, l3);
    hi[4 * i + 0] = h0; hi[4 * i + 1] = h1; hi[4 * i + 2] = h2; hi[4 * i + 3] = h3;
    lo[4 * i + 0] = l0; lo[4 * i + 1] = l1; lo[4 * i + 2] = l2; lo[4 * i + 3] = l3;
}

__global__ void convert_wT_kernel(const float* __restrict__ w,
                                  __nv_bfloat16* __restrict__ hi,
                                  __nv_bfloat16* __restrict__ lo, int K, int Nn) {
    int i = blockIdx.x * blockDim.x + threadIdx.x;
    if (i >= K * Nn) return;
    int n = i / K, k = i - n * K;
    float v = w[(size_t)k * Nn + n];
    __nv_bfloat16 h, l;
    bf_split(v, h, l);
    hi[i] = h; lo[i] = l;
}

// -------------------- mma.sync split-bf16 GEMM (double-buffered) -------------
#define TILE_B   (128 * 144)        // 18432 bytes per operand tile
#define BUF_B    (4 * TILE_B)       // 73728 per stage
#define GEMM_SMEM (2 * BUF_B)       // 147456

template <int MODE>
__global__ __launch_bounds__(256, 1) void mma_gemm_kernel(
    const __nv_bfloat16* __restrict__ Ahi, const __nv_bfloat16* __restrict__ Alo,
    const __nv_bfloat16* __restrict__ Bhi, const __nv_bfloat16* __restrict__ Blo,
    const float* __restrict__ bias, float* __restrict__ outp)
{
    extern __shared__ char sm[];
    const uint32_t smb = smem_to_u32(sm);
    const int tid = threadIdx.x;
    const int lane = tid & 31;
    const int wid = tid >> 5;
    const int wm = wid & 1;
    const int wn = wid >> 1;
    const int row0 = blockIdx.y * 128;
    const int col0 = blockIdx.x * 128;

    float c[4][4][4];
    #pragma unroll
    for (int i = 0; i < 4; i++)
        #pragma unroll
        for (int j = 0; j < 4; j++)
            #pragma unroll
            for (int e = 0; e < 4; e++) c[i][j][e] = 0.f;

    const int frow = tid >> 3;
    const int fcol = tid & 7;

    const uint32_t offA = (uint32_t)(wm * 64 + (lane & 15)) * 144 + ((lane >> 4) << 3) * 2;
    const uint32_t offB = (uint32_t)(wn * 32 + ((lane >> 4) << 3) + (lane & 7)) * 144 +
                          (((lane >> 3) & 1) << 3) * 2;

    auto prefetch = [&](int kb, int buf) {
        uint32_t sb = smb + buf * BUF_B;
        #pragma unroll
        for (int i = 0; i < 4; i++) {
            int row = frow + 32 * i;
            size_t gA = (size_t)(row0 + row) * PDIM + kb * 64 + fcol * 8;
            size_t gB = (size_t)(col0 + row) * PDIM + kb * 64 + fcol * 8;
            uint32_t so = (uint32_t)row * 144 + fcol * 16;
            cp_async16(sb + 0 * TILE_B + so, Ahi + gA);
            cp_async16(sb + 1 * TILE_B + so, Alo + gA);
            cp_async16(sb + 2 * TILE_B + so, Bhi + gB);
            cp_async16(sb + 3 * TILE_B + so, Blo + gB);
        }
        CP_COMMIT();
    };

    prefetch(0, 0);

    for (int kb = 0; kb < 8; kb++) {
        if (kb + 1 < 8) {
            prefetch(kb + 1, (kb + 1) & 1);
            CP_WAIT(1);
        } else {
            CP_WAIT(0);
        }
        __syncthreads();

        const uint32_t sb = smb + (kb & 1) * BUF_B;
        #pragma unroll
        for (int ks = 0; ks < 4; ks++) {
            uint32_t ah[4][4], al[4][4], bhv[2][4], blv[2][4];
            #pragma unroll
            for (int mf = 0; mf < 4; mf++) {
                ldsm4(ah[mf], sb + 0 * TILE_B + offA + mf * (16 * 144) + ks * 32);
                ldsm4(al[mf], sb + 1 * TILE_B + offA + mf * (16 * 144) + ks * 32);
            }
            #pragma unroll
            for (int nb = 0; nb < 2; nb++) {
                ldsm4(bhv[nb], sb + 2 * TILE_B + offB + nb * (16 * 144) + ks * 32);
                ldsm4(blv[nb], sb + 3 * TILE_B + offB + nb * (16 * 144) + ks * 32);
            }
            #pragma unroll
            for (int mf = 0; mf < 4; mf++) {
                #pragma unroll
                for (int nf = 0; nf < 4; nf++) {
                    const uint32_t* ph = &bhv[nf >> 1][(nf & 1) * 2];
                    const uint32_t* pl = &blv[nf >> 1][(nf & 1) * 2];
                    mma16816(c[mf][nf], ah[mf], ph);
                    mma16816(c[mf][nf], ah[mf], pl);
                    mma16816(c[mf][nf], al[mf], ph);
                }
            }
        }
        __syncthreads();
    }

    float* ts = (float*)sm;
    const int g = lane >> 2, tg = lane & 3;
    #pragma unroll
    for (int mf = 0; mf < 4; mf++) {
        #pragma unroll
        for (int nf = 0; nf < 4; nf++) {
            int r = wm * 64 + mf * 16 + g;
            int cc = wn * 32 + nf * 8 + 2 * tg;
            ts[r * 132 + cc]           = c[mf][nf][0];
            ts[r * 132 + cc + 1]       = c[mf][nf][1];
            ts[(r + 8) * 132 + cc]     = c[mf][nf][2];
            ts[(r + 8) * 132 + cc + 1] = c[mf][nf][3];
        }
    }
    __syncthreads();

    if (MODE == 0) {
        int which = col0 >> 9;
        int c0 = col0 & 511;
        int h0 = c0 >> 6;
        float* dst = which == 0 ? g_q : (which == 1 ? g_k : g_v);
        float scale = which == 0 ? 0.125f : 1.0f;
        #pragma unroll
        for (int t = 0; t < 16; t++) {
            int idx = tid + t * 256;
            int row = idx >> 5;
            int cc = (idx & 31) * 4;
            int m = row0 + row;
            if (m >= PM1) continue;
            int b = m / PN, n = m - b * PN;
            int h = h0 + (cc >> 6), d = cc & 63;
            float4 v = *(float4*)&ts[row * 132 + cc];
            v.x *= scale; v.y *= scale; v.z *= scale; v.w *= scale;
            *(float4*)&dst[(((size_t)(b * PH + h) * PN + n) << 6) + d] = v;
        }
    } else {
        #pragma unroll
        for (int t = 0; t < 16; t++) {
            int idx = tid + t * 256;
            int row = idx >> 5;
            int cc = (idx & 31) * 4;
            int m = row0 + row;
            if (m >= PM1) continue;
            int col = col0 + cc;
            float4 v = *(float4*)&ts[row * 132 + cc];
            float4 bv = *(const float4*)&bias[col];
            v.x += bv.x; v.y += bv.y; v.z += bv.z; v.w += bv.w;
            *(float4*)&outp[(size_t)m * PDIM + col] = v;
        }
    }
}

// -------------------- joints attention ---------------------------------------
#define J1_SMEM (PJ * PDH * 4 + PDH * 257 * 4)   // 71936

__global__ __launch_bounds__(64) void joints_logits_kernel()
{
    extern __shared__ float smf[];
    float* qs  = smf;                 // [24][64]
    float* ksT = smf + PJ * PDH;      // [64][257]

    const int bh = blockIdx.y;
    const int kb = blockIdx.x;
    const int tid = threadIdx.x;
    const int n0 = kb * 256;
    const size_t base = (size_t)bh * PN * PDH;

    #pragma unroll
    for (int i = 0; i < 24; i++)
        qs[tid + 64 * i] = g_q[base + tid + 64 * i];

    #pragma unroll 8
    for (int i = 0; i < 64; i++) {
        int idx = tid + 64 * i;
        int key = idx >> 4;
        int d4 = (idx & 15) << 2;
        int n = n0 + key;
        if (n < PN) {
            float4 v = *(const float4*)&g_k[base + (size_t)n * PDH + d4];
            ksT[(d4 + 0) * 257 + key] = v.x;
            ksT[(d4 + 1) * 257 + key] = v.y;
            ksT[(d4 + 2) * 257 + key] = v.z;
            ksT[(d4 + 3) * 257 + key] = v.w;
        }
    }
    __syncthreads();

    float acc[24][4];
    #pragma unroll
    for (int j = 0; j < 24; j++)
        #pragma unroll
        for (int s = 0; s < 4; s++) acc[j][s] = 0.f;

    for (int d = 0; d < PDH; d++) {
        float k0 = ksT[d * 257 + tid];
        float k1 = ksT[d * 257 + tid + 64];
        float k2 = ksT[d * 257 + tid + 128];
        float k3 = ksT[d * 257 + tid + 192];
        #pragma unroll
        for (int j = 0; j < 24; j++) {
            float qv = qs[j * 64 + d];
            acc[j][0] += qv * k0;
            acc[j][1] += qv * k1;
            acc[j][2] += qv * k2;
            acc[j][3] += qv * k3;
        }
    }

    #pragma unroll
    for (int s = 0; s < 4; s++) {
        int n = n0 + tid + 64 * s;
        if (n < PN) {
            #pragma unroll
            for (int j = 0; j < 24; j++)
                g_jp[((size_t)bh * PJ + j) * PN + n] = __expf(acc[j][s]);
        }
    }
}

#define J2_SMEM (256 * PDH * 4 + PJ * 256 * 4)    // 90112

__global__ __launch_bounds__(256) void joints_pv_kernel()
{
    extern __shared__ float smf[];
    float* vs = smf;                  // [256][64]
    float* ps = smf + 256 * PDH;      // [24][256]

    const int bh = blockIdx.y;
    const int bx = blockIdx.x;
    const int tid = threadIdx.x;
    const int d = tid & 63;
    const int jg = tid >> 6;
    const int n0 = bx * JCHUNK;
    int total = PN - n0; if (total > JCHUNK) total = JCHUNK;
    const size_t base = (size_t)bh * PN * PDH;

    float out[6], psum[6];
    #pragma unroll
    for (int t = 0; t < 6; t++) { out[t] = 0.f; psum[t] = 0.f; }

    for (int c = 0; c < 4; c++) {
        int n0c = n0 + c * 256;
        int cnt = total - c * 256;
        if (cnt <= 0) break;
        if (cnt > 256) cnt = 256;

        #pragma unroll
        for (int t = 0; t < 16; t++) {
            int idx = tid + t * 256;
            int key = idx >> 4;
            int d4 = (idx & 15) << 2;
            float4 v = make_float4(0.f, 0.f, 0.f, 0.f);
            if (key < cnt) v = *(const float4*)&g_v[base + (size_t)(n0c + key) * PDH + d4];
            *(float4*)&vs[key * PDH + d4] = v;
        }
        #pragma unroll
        for (int t = 0; t < 6; t++) {
            int idx = tid + t * 256;
            int j = idx >> 6;
            int nn4 = (idx & 63) << 2;
            float4 v;
            if (nn4 + 3 < cnt) {
                v = *(const float4*)&g_jp[((size_t)bh * PJ + j) * PN + n0c + nn4];
            } else {
                float tmp[4];
                #pragma unroll
                for (int e = 0; e < 4; e++)
                    tmp[e] = (nn4 + e < cnt)
                        ? g_jp[((size_t)bh * PJ + j) * PN + n0c + nn4 + e] : 0.f;
                v = make_float4(tmp[0], tmp[1], tmp[2], tmp[3]);
            }
            *(float4*)&ps[j * 256 + nn4] = v;
        }
        __syncthreads();

        for (int nn = 0; nn < 256; nn += 4) {
            float v0 = vs[(nn + 0) * PDH + d];
            float v1 = vs[(nn + 1) * PDH + d];
            float v2 = vs[(nn + 2) * PDH + d];
            float v3 = vs[(nn + 3) * PDH + d];
            #pragma unroll
            for (int t = 0; t < 6; t++) {
                int j = jg + 4 * t;
                float4 p4 = *(float4*)&ps[j * 256 + nn];
                out[t] += p4.x * v0 + p4.y * v1 + p4.z * v2 + p4.w * v3;
                psum[t] += p4.x + p4.y + p4.z + p4.w;
            }
        }
        __syncthreads();
    }

    #pragma unroll
    for (int t = 0; t < 6; t++) {
        int j = jg + 4 * t;
        g_jout[(((size_t)bx * PBH + bh) * PJ + j) * PDH + d] = out[t];
        if (d == 0) g_jpsum[((size_t)bx * PBH + bh) * PJ + j] = psum[t];
    }
}

// J3: combine partials, divide, write bf16 hi/lo directly
__global__ __launch_bounds__(256) void joints_finish_kernel()
{
    const int bh = blockIdx.x;
    const int tid = threadIdx.x;
    const int d = tid & 63;
    const int jg = tid >> 6;
    const int b = bh >> 3, h = bh & 7;
    #pragma unroll
    for (int t = 0; t < 6; t++) {
        int j = jg + 4 * t;
        float o = 0.f, s = 0.f;
        #pragma unroll
        for (int bx = 0; bx < 4; bx++) {
            o += g_jout[(((size_t)bx * PBH + bh) * PJ + j) * PDH + d];
            s += g_jpsum[((size_t)bx * PBH + bh) * PJ + j];
        }
        float v = o / s;
        size_t off = (size_t)(b * PN + j) * PDIM + h * PDH + d;
        __nv_bfloat16 hh, ll;
        bf_split(v, hh, ll);
        g_ohi[off] = hh;
        g_olo[off] = ll;
    }
}

// -------------------- spatial attention (no-max, packed f32x2) ----------------
// 256 threads, 1 CTA/SM. Per-key inner loop halved via FFMA2 (fma.rn.f32x2):
// 32 ffma2 for the dot + 32 ffma2 for PV accumulation. K/V read from smem as
// ulonglong2 (LDS.128 into 64-bit pairs, warp-uniform -> broadcast).
#define SPATIAL_SMEM (2 * NKEY * PDH * (int)sizeof(float))

__global__ __launch_bounds__(256, 1) void spatial_attn_kernel(
    const float* __restrict__ sinp, const float* __restrict__ cosp)
{
    extern __shared__ float smf[];
    float* ks = smf;
    float* vs = smf + NKEY * PDH;

    const int bh = blockIdx.y;
    const int f  = blockIdx.x;
    const int tid = threadIdx.x;
    const size_t base = (size_t)bh * PN * PDH;

    for (int idx = tid; idx < NKEY * PDH; idx += 256) {
        int nrow = idx >> 6;
        int d = idx & 63;
        int gn = (nrow < PJ) ? nrow : (PJ + f * PNS + (nrow - PJ));
        float kv = g_k[base + (size_t)gn * PDH + d];
        float vv = g_v[base + (size_t)gn * PDH + d];
        if (nrow >= PJ && d < PROT) {
            int s = nrow - PJ;
            float c = cosp[s * PROT + d];
            float sn = sinp[s * PROT + d];
            float partner = g_k[base + (size_t)gn * PDH + (d ^ 1)];
            kv = (d & 1) ? (kv * c + partner * sn) : (kv * c - partner * sn);
        }
        ks[idx] = kv;
        vs[idx] = vv;
    }
    __syncthreads();

    if (tid < PNS) {
        const int s = tid;
        const int gn = PJ + f * PNS + s;

        float4 q4[16];
        const float4* qp = (const float4*)(g_q + base + (size_t)gn * PDH);
        #pragma unroll
        for (int i = 0; i < 16; i++) q4[i] = qp[i];

        // RoPE on first 32 dims
        #pragma unroll
        for (int i = 0; i < 8; i++) {
            int d0 = 4 * i;
            float c0 = cosp[s * PROT + d0],     s0 = sinp[s * PROT + d0];
            float c1 = cosp[s * PROT + d0 + 1], s1 = sinp[s * PROT + d0 + 1];
            float c2 = cosp[s * PROT + d0 + 2], s2 = sinp[s * PROT + d0 + 2];
            float c3 = cosp[s * PROT + d0 + 3], s3 = sinp[s * PROT + d0 + 3];
            float ax = q4[i].x, ay = q4[i].y, az = q4[i].z, aw = q4[i].w;
            q4[i].x = ax * c0 - ay * s0;
            q4[i].y = ay * c1 + ax * s1;
            q4[i].z = az * c2 - aw * s2;
            q4[i].w = aw * c3 + az * s3;
        }

        // pack q into 32 f32x2 pairs
        uint64_t q2[32];
        #pragma unroll
        for (int i = 0; i < 16; i++) {
            q2[2 * i]     = pk2(q4[i].x, q4[i].y);
            q2[2 * i + 1] = pk2(q4[i].z, q4[i].w);
        }

        float l = 0.f;
        uint64_t o2[32];
        #pragma unroll
        for (int i = 0; i < 32; i++) o2[i] = 0ull;

        for (int n = 0; n < NKEY; n++) {
            const ulonglong2* kp = (const ulonglong2*)&ks[n * PDH];
            uint64_t da = 0ull, db = 0ull;
            #pragma unroll
            for (int i = 0; i < 8; i++) {
                ulonglong2 kk = kp[i];
                ffma2(da, q2[2 * i], kk.x);
                ffma2(db, q2[2 * i + 1], kk.y);
            }
            #pragma unroll
            for (int i = 8; i < 16; i++) {
                ulonglong2 kk = kp[i];
                ffma2(da, q2[2 * i], kk.x);
                ffma2(db, q2[2 * i + 1], kk.y);
            }
            float a0, a1, b0, b1;
            upk2(da, a0, a1); upk2(db, b0, b1);
            float p = __expf((a0 + a1) + (b0 + b1));
            l += p;
            uint64_t pp = pk2(p, p);
            const ulonglong2* vp = (const ulonglong2*)&vs[n * PDH];
            #pragma unroll
            for (int i = 0; i < 16; i++) {
                ulonglong2 vv = vp[i];
                ffma2(o2[2 * i], pp, vv.x);
                ffma2(o2[2 * i + 1], pp, vv.y);
            }
        }

        const float inv = 1.f / l;
        const int b = bh >> 3, h = bh & 7;
        size_t off = (size_t)(b * PN + gn) * PDIM + h * PDH;
        __nv_bfloat16* ohp = g_ohi + off;
        __nv_bfloat16* olp = g_olo + off;
        #pragma unroll
        for (int i = 0; i < 32; i++) {
            float v0, v1;
            upk2(o2[i], v0, v1);
            v0 *= inv; v1 *= inv;
            __nv_bfloat16 h0, l0, h1, l1;
            bf_split(v0, h0, l0);
            bf_split(v1, h1, l1);
            ohp[2 * i] = h0; ohp[2 * i + 1] = h1;
            olp[2 * i] = l0; olp[2 * i + 1] = l1;
        }
    }
}

// -------------------- launch --------------------------------------------------
extern "C" void kernel_launch(void* const* d_in, const int* in_sizes, int n_in,
                              void* d_out, int out_size)
{
    (void)in_sizes; (void)n_in; (void)out_size;
    const float* x      = (const float*)d_in[0];
    const float* w_qkv  = (const float*)d_in[1];
    const float* w_out  = (const float*)d_in[2];
    const float* b_out  = (const float*)d_in[3];
    const float* sinp   = (const float*)d_in[4];
    const float* cosp   = (const float*)d_in[5];
    float* out = (float*)d_out;

    cudaFuncSetAttribute(spatial_attn_kernel,
                         cudaFuncAttributeMaxDynamicSharedMemorySize, SPATIAL_SMEM);
    cudaFuncSetAttribute(mma_gemm_kernel<0>,
                         cudaFuncAttributeMaxDynamicSharedMemorySize, GEMM_SMEM);
    cudaFuncSetAttribute(mma_gemm_kernel<1>,
                         cudaFuncAttributeMaxDynamicSharedMemorySize, GEMM_SMEM);
    cudaFuncSetAttribute(joints_logits_kernel,
                         cudaFuncAttributeMaxDynamicSharedMemorySize, J1_SMEM);
    cudaFuncSetAttribute(joints_pv_kernel,
                         cudaFuncAttributeMaxDynamicSharedMemorySize, J2_SMEM);

    __nv_bfloat16 *xhi, *xlo, *ohi, *olo, *wqh, *wql, *woh, *wol;
    cudaGetSymbolAddress((void**)&xhi, g_xhi);
    cudaGetSymbolAddress((void**)&xlo, g_xlo);
    cudaGetSymbolAddress((void**)&ohi, g_ohi);
    cudaGetSymbolAddress((void**)&olo, g_olo);
    cudaGetSymbolAddress((void**)&wqh, g_wqkvT_hi);
    cudaGetSymbolAddress((void**)&wql, g_wqkvT_lo);
    cudaGetSymbolAddress((void**)&woh, g_woutT_hi);
    cudaGetSymbolAddress((void**)&wol, g_woutT_lo);

    // 1) split-convert x and transpose-convert weights
    {
        int n4 = PM1 * PDIM / 4;
        convert_split_kernel<<<(n4 + 255) / 256, 256>>>(x, xhi, xlo, n4);
        int nw = PDIM * NQKV;
        convert_wT_kernel<<<(nw + 255) / 256, 256>>>(w_qkv, wqh, wql, PDIM, NQKV);
        int nw2 = PDIM * PDIM;
        convert_wT_kernel<<<(nw2 + 255) / 256, 256>>>(w_out, woh, wol, PDIM, PDIM);
    }

    // 2) QKV projection (tensor cores, cp.async double-buffered)
    mma_gemm_kernel<0><<<dim3(NQKV / 128, (PM1 + 127) / 128), 256, GEMM_SMEM>>>(
        xhi, xlo, wqh, wql, nullptr, nullptr);

    // 3) joints attention (writes g_ohi/g_olo rows n<24 directly)
    joints_logits_kernel<<<dim3((PN + 255) / 256, PBH), 64, J1_SMEM>>>();
    joints_pv_kernel<<<dim3(4, PBH), 256, J2_SMEM>>>();
    joints_finish_kernel<<<PBH, 256>>>();

    // 4) spatial attention (writes g_ohi/g_olo rows n>=24 directly)
    spatial_attn_kernel<<<dim3(PF, PBH), 256, SPATIAL_SMEM>>>(sinp, cosp);

    // 5) output projection + bias (consumes g_ohi/g_olo directly)
    mma_gemm_kernel<1><<<dim3(PDIM / 128, (PM1 + 127) / 128), 256, GEMM_SMEM>>>(
        ohi, olo, woh, wol, b_out, out);
}